// round 6
// baseline (speedup 1.0000x reference)
#include <cuda_runtime.h>
#include <cuda_bf16.h>
#include <cstdint>

#define BB 256
#define NIN 2048
#define NH 2048
#define NC 100
#define NCP 128
#define TSTEPS 25
#define MT (TSTEPS*BB)   // 6400
#define BETA 0.95f
#define THRESH 1.0f

typedef __nv_bfloat16 bf16;

// ---------------- scratch (device globals; no allocations allowed) -----------
__device__ __align__(256) bf16 g_w2h[NH*NH],  g_w2m[NH*NH],  g_w2l[NH*NH];
__device__ __align__(256) bf16 g_w3h[NCP*NH], g_w3m[NCP*NH], g_w3l[NCP*NH];
__device__ __align__(256) float g_b3p[NCP];
__device__ __align__(256) float g_C1[BB*NH];        // cur1 (+b1), loop-invariant
__device__ __align__(256) bf16  g_spk1[MT*NH];      // [t][b][n]
__device__ __align__(256) float g_C2[MT*NH];
__device__ __align__(256) bf16  g_spk2[MT*NH];
__device__ __align__(256) float g_C3[MT*NCP];

// ---------------- 3-way bf16 split (exact decomposition) ---------------------
__global__ void conv3_kernel(const float* __restrict__ src,
                             bf16* __restrict__ h, bf16* __restrict__ m,
                             bf16* __restrict__ l, int n)
{
    int i = blockIdx.x * blockDim.x + threadIdx.x;
    if (i >= n) return;
    float v  = src[i];
    bf16 hv  = __float2bfloat16_rn(v);
    float r1 = v - __bfloat162float(hv);
    bf16 mv  = __float2bfloat16_rn(r1);
    float r2 = r1 - __bfloat162float(mv);
    h[i] = hv; m[i] = mv; l[i] = __float2bfloat16_rn(r2);
}

__global__ void conv3_w3_kernel(const float* __restrict__ W3)
{
    int i = blockIdx.x * blockDim.x + threadIdx.x;   // 0 .. NCP*NH-1
    if (i >= NCP * NH) return;
    int row = i >> 11;
    float v = (row < NC) ? W3[(size_t)row * NH + (i & (NH - 1))] : 0.0f;
    bf16 hv  = __float2bfloat16_rn(v);
    float r1 = v - __bfloat162float(hv);
    bf16 mv  = __float2bfloat16_rn(r1);
    float r2 = r1 - __bfloat162float(mv);
    g_w3h[i] = hv; g_w3m[i] = mv; g_w3l[i] = __float2bfloat16_rn(r2);
}

__global__ void b3pad_kernel(const float* __restrict__ b3)
{
    int i = threadIdx.x;
    if (i < NCP) g_b3p[i] = (i < NC) ? b3[i] : 0.0f;
}

// ---------------- GEMM1: fp32 SIMT, K sequential (bitwise = round 3) ---------
// BM=32, BN=64, BK=16; 256 threads; per-thread tile 2x4. grid (8, 32).
__global__ void __launch_bounds__(256)
gemm1_f32_kernel(const float* __restrict__ A, const float* __restrict__ W,
                 const float* __restrict__ bias, float* __restrict__ Cout)
{
    __shared__ float As[16][32];
    __shared__ float Bs[16][64];

    const int bm  = blockIdx.x * 32;
    const int bn  = blockIdx.y * 64;
    const int tid = threadIdx.x;
    const int tr  = tid >> 4;         // 0..15 (row pairs)
    const int tc  = tid & 15;         // 0..15 (col groups of 4)
    const int lr  = tid >> 2;         // 0..63
    const int lc  = (tid & 3) << 2;   // 0,4,8,12

    float acc[2][4];
#pragma unroll
    for (int i = 0; i < 2; i++)
#pragma unroll
        for (int j = 0; j < 4; j++) acc[i][j] = 0.0f;

    const float* Aptr = A + (size_t)(bm + lr) * NIN + lc;
    const float* Wptr = W + (size_t)(bn + lr) * NIN + lc;

    for (int k0 = 0; k0 < NIN; k0 += 16) {
        if (lr < 32) {
            float4 av = *(const float4*)(Aptr + k0);
            As[lc + 0][lr] = av.x; As[lc + 1][lr] = av.y;
            As[lc + 2][lr] = av.z; As[lc + 3][lr] = av.w;
        }
        {
            float4 wv = *(const float4*)(Wptr + k0);
            Bs[lc + 0][lr] = wv.x; Bs[lc + 1][lr] = wv.y;
            Bs[lc + 2][lr] = wv.z; Bs[lc + 3][lr] = wv.w;
        }
        __syncthreads();
#pragma unroll
        for (int k = 0; k < 16; k++) {
            float a0 = As[k][tr * 2];
            float a1 = As[k][tr * 2 + 1];
            float b[4];
            *(float4*)b = *(const float4*)&Bs[k][tc * 4];
#pragma unroll
            for (int j = 0; j < 4; j++) {
                acc[0][j] += a0 * b[j];
                acc[1][j] += a1 * b[j];
            }
        }
        __syncthreads();
    }

#pragma unroll
    for (int i = 0; i < 2; i++) {
        int r = bm + tr * 2 + i;
#pragma unroll
        for (int j = 0; j < 4; j++) {
            int c = bn + tc * 4 + j;
            Cout[(size_t)r * NH + c] = acc[i][j] + bias[c];
        }
    }
}

// ---------------- MMA helpers -------------------------------------------------
__device__ __forceinline__ uint32_t smem_u32(const void* p) {
    return (uint32_t)__cvta_generic_to_shared(p);
}
__device__ __forceinline__ void cp16(uint32_t dst, const void* src) {
    asm volatile("cp.async.ca.shared.global [%0], [%1], 16;" :: "r"(dst), "l"(src));
}
__device__ __forceinline__ void cp_commit() { asm volatile("cp.async.commit_group;"); }
template<int N> __device__ __forceinline__ void cp_wait() {
    asm volatile("cp.async.wait_group %0;" :: "n"(N));
}
__device__ __forceinline__ void ldm_x4(uint32_t* r, uint32_t addr) {
    asm volatile("ldmatrix.sync.aligned.m8n8.x4.shared.b16 {%0,%1,%2,%3}, [%4];"
                 : "=r"(r[0]), "=r"(r[1]), "=r"(r[2]), "=r"(r[3]) : "r"(addr));
}
__device__ __forceinline__ void mma16816(float* c, const uint32_t* a,
                                          uint32_t b0, uint32_t b1) {
    asm volatile(
        "mma.sync.aligned.m16n8k16.row.col.f32.bf16.bf16.f32 "
        "{%0,%1,%2,%3}, {%4,%5,%6,%7}, {%8,%9}, {%0,%1,%2,%3};"
        : "+f"(c[0]), "+f"(c[1]), "+f"(c[2]), "+f"(c[3])
        : "r"(a[0]), "r"(a[1]), "r"(a[2]), "r"(a[3]), "r"(b0), "r"(b1));
}

// ======== GEMM2: BM=128, BN=128, BK=32; twin accumulators (h | m,l) ==========
// 256 threads = 8 warps (2M x 4N), warp tile 64x32, MI=4. Bitwise = round 3.
#define A_STG2 (128*40*2)     // 10240 B per stage
#define B_STG2 (128*40*2)

__global__ void __launch_bounds__(256)
mma3_gemm_k128(const bf16* __restrict__ A,
               const bf16* __restrict__ B0, const bf16* __restrict__ B1,
               const bf16* __restrict__ B2,
               const float* __restrict__ bias, float* __restrict__ C,
               int K, int N)
{
    __shared__ bf16 As[2][128][40];
    __shared__ bf16 Bs[2][128][40];

    const int tid  = threadIdx.x;
    const int lane = tid & 31;
    const int wid  = tid >> 5;
    const int wm   = wid >> 2;      // 0..1
    const int wn   = wid & 3;       // 0..3
    const int g    = lane >> 2;
    const int q    = lane & 3;
    const int bm   = blockIdx.x * 128;
    const int bn   = blockIdx.y * 128;
    const bf16* Bp[3] = {B0, B1, B2};

    const uint32_t As_base = smem_u32(&As[0][0][0]);
    const uint32_t Bs_base = smem_u32(&Bs[0][0][0]);

    uint32_t a_off[4];
#pragma unroll
    for (int i = 0; i < 4; i++)
        a_off[i] = ((wm * 64 + i * 16 + (lane & 15)) * 40 + ((lane >> 4) & 1) * 8) * 2;
    uint32_t b_off[2];
#pragma unroll
    for (int jj = 0; jj < 2; jj++)
        b_off[jj] = ((wn * 32 + jj * 16 + ((lane >> 4) & 1) * 8 + (lane & 7)) * 40
                     + ((lane >> 3) & 1) * 8) * 2;

    float acc_h[4][4][4], acc_ml[4][4][4];
#pragma unroll
    for (int i = 0; i < 4; i++)
#pragma unroll
        for (int j = 0; j < 4; j++)
#pragma unroll
            for (int r = 0; r < 4; r++) { acc_h[i][j][r] = 0.0f; acc_ml[i][j][r] = 0.0f; }

    const int ktiles = K / 32;
    const int ktot   = ktiles * 3;

    auto issue = [&](int tn, int st) {
        int p  = tn / ktiles;
        int kc = (tn - p * ktiles) * 32;
        const bf16* Bq = Bp[p];
#pragma unroll
        for (int r = 0; r < 2; r++) {
            int u = tid + r * 256, row = u >> 2, c8 = (u & 3) * 8;
            cp16(As_base + st * A_STG2 + (row * 40 + c8) * 2,
                 A + (size_t)(bm + row) * K + kc + c8);
            cp16(Bs_base + st * B_STG2 + (row * 40 + c8) * 2,
                 Bq + (size_t)(bn + row) * K + kc + c8);
        }
        cp_commit();
    };

    issue(0, 0);

    for (int kt = 0; kt < ktot; kt++) {
        const int st = kt & 1;
        if (kt + 1 < ktot) { issue(kt + 1, (kt + 1) & 1); cp_wait<1>(); }
        else               { cp_wait<0>(); }
        __syncthreads();

        const bool is_h = (kt < ktiles);
#pragma unroll
        for (int kk = 0; kk < 32; kk += 16) {
            uint32_t af[4][4], bf[2][4];
#pragma unroll
            for (int i = 0; i < 4; i++)
                ldm_x4(af[i], As_base + st * A_STG2 + a_off[i] + kk * 2);
#pragma unroll
            for (int jj = 0; jj < 2; jj++)
                ldm_x4(bf[jj], Bs_base + st * B_STG2 + b_off[jj] + kk * 2);

            if (is_h) {
#pragma unroll
                for (int i = 0; i < 4; i++)
#pragma unroll
                    for (int j = 0; j < 4; j++)
                        mma16816(acc_h[i][j], af[i], bf[j >> 1][(j & 1) * 2],
                                 bf[j >> 1][(j & 1) * 2 + 1]);
            } else {
#pragma unroll
                for (int i = 0; i < 4; i++)
#pragma unroll
                    for (int j = 0; j < 4; j++)
                        mma16816(acc_ml[i][j], af[i], bf[j >> 1][(j & 1) * 2],
                                 bf[j >> 1][(j & 1) * 2 + 1]);
            }
        }
        __syncthreads();
    }

#pragma unroll
    for (int i = 0; i < 4; i++) {
        int r0 = bm + wm * 64 + i * 16 + g;
#pragma unroll
        for (int j = 0; j < 4; j++) {
            int c0 = bn + wn * 32 + j * 8 + q * 2;
            float bv0 = bias[c0], bv1 = bias[c0 + 1];
            C[(size_t)r0 * N + c0]           = acc_h[i][j][0] + acc_ml[i][j][0] + bv0;
            C[(size_t)r0 * N + c0 + 1]       = acc_h[i][j][1] + acc_ml[i][j][1] + bv1;
            C[(size_t)(r0 + 8) * N + c0]     = acc_h[i][j][2] + acc_ml[i][j][2] + bv0;
            C[(size_t)(r0 + 8) * N + c0 + 1] = acc_h[i][j][3] + acc_ml[i][j][3] + bv1;
        }
    }
}

// ======== GEMM3: BM=64, BN=128 (round-3 kernel, bitwise identical) ===========
#define MMA_BM 64
#define MMA_MI 2
#define A_STG (MMA_BM*40*2)     // 5120 B per stage
#define B_STG (128*40*2)        // 10240 B per stage

__global__ void __launch_bounds__(256)
mma3_gemm(const bf16* __restrict__ A,
          const bf16* __restrict__ B0, const bf16* __restrict__ B1,
          const bf16* __restrict__ B2,
          const float* __restrict__ bias, float* __restrict__ C,
          int K, int N)
{
    __shared__ bf16 As[2][MMA_BM][40];
    __shared__ bf16 Bs[2][128][40];

    const int tid  = threadIdx.x;
    const int lane = tid & 31;
    const int wid  = tid >> 5;
    const int wm   = wid >> 2;
    const int wn   = wid & 3;
    const int g    = lane >> 2;
    const int q    = lane & 3;
    const int bm   = blockIdx.x * MMA_BM;
    const int bn   = blockIdx.y * 128;

    const uint32_t As_base = smem_u32(&As[0][0][0]);
    const uint32_t Bs_base = smem_u32(&Bs[0][0][0]);

    uint32_t a_off[MMA_MI];
#pragma unroll
    for (int i = 0; i < MMA_MI; i++)
        a_off[i] = ((wm * 32 + i * 16 + (lane & 15)) * 40 + ((lane >> 4) & 1) * 8) * 2;
    uint32_t b_off[2];
#pragma unroll
    for (int jj = 0; jj < 2; jj++)
        b_off[jj] = ((wn * 32 + jj * 16 + ((lane >> 4) & 1) * 8 + (lane & 7)) * 40
                     + ((lane >> 3) & 1) * 8) * 2;

    const int arow = tid >> 2, ac8 = (tid & 3) * 8;

    float acc_h[MMA_MI][4][4], acc_ml[MMA_MI][4][4];
#pragma unroll
    for (int i = 0; i < MMA_MI; i++)
#pragma unroll
        for (int j = 0; j < 4; j++)
#pragma unroll
            for (int r = 0; r < 4; r++) { acc_h[i][j][r] = 0.0f; acc_ml[i][j][r] = 0.0f; }

    const int ktiles = K / 32;
    const int ktot   = ktiles * 3;

    auto issue = [&](int tn, int st) {
        int p  = tn / ktiles;
        int kc = (tn - p * ktiles) * 32;
        const bf16* Bp = (p == 0) ? B0 : ((p == 1) ? B1 : B2);
        cp16(As_base + st * A_STG + (arow * 40 + ac8) * 2,
             A + (size_t)(bm + arow) * K + kc + ac8);
#pragma unroll
        for (int r = 0; r < 2; r++) {
            int u = tid + r * 256, row = u >> 2, c8 = (u & 3) * 8;
            cp16(Bs_base + st * B_STG + (row * 40 + c8) * 2,
                 Bp + (size_t)(bn + row) * K + kc + c8);
        }
        cp_commit();
    };

    issue(0, 0);

    for (int kt = 0; kt < ktot; kt++) {
        const int st = kt & 1;
        if (kt + 1 < ktot) { issue(kt + 1, (kt + 1) & 1); cp_wait<1>(); }
        else               { cp_wait<0>(); }
        __syncthreads();

        const bool is_h = (kt < ktiles);
#pragma unroll
        for (int kk = 0; kk < 32; kk += 16) {
            uint32_t af[MMA_MI][4], bf[2][4];
#pragma unroll
            for (int i = 0; i < MMA_MI; i++)
                ldm_x4(af[i], As_base + st * A_STG + a_off[i] + kk * 2);
#pragma unroll
            for (int jj = 0; jj < 2; jj++)
                ldm_x4(bf[jj], Bs_base + st * B_STG + b_off[jj] + kk * 2);

            if (is_h) {
#pragma unroll
                for (int i = 0; i < MMA_MI; i++)
#pragma unroll
                    for (int j = 0; j < 4; j++)
                        mma16816(acc_h[i][j], af[i], bf[j >> 1][(j & 1) * 2],
                                 bf[j >> 1][(j & 1) * 2 + 1]);
            } else {
#pragma unroll
                for (int i = 0; i < MMA_MI; i++)
#pragma unroll
                    for (int j = 0; j < 4; j++)
                        mma16816(acc_ml[i][j], af[i], bf[j >> 1][(j & 1) * 2],
                                 bf[j >> 1][(j & 1) * 2 + 1]);
            }
        }
        __syncthreads();
    }

#pragma unroll
    for (int i = 0; i < MMA_MI; i++) {
        int r0 = bm + wm * 32 + i * 16 + g;
#pragma unroll
        for (int j = 0; j < 4; j++) {
            int c0 = bn + wn * 32 + j * 8 + q * 2;
            float bv0 = bias[c0], bv1 = bias[c0 + 1];
            C[(size_t)r0 * N + c0]           = acc_h[i][j][0] + acc_ml[i][j][0] + bv0;
            C[(size_t)r0 * N + c0 + 1]       = acc_h[i][j][1] + acc_ml[i][j][1] + bv1;
            C[(size_t)(r0 + 8) * N + c0]     = acc_h[i][j][2] + acc_ml[i][j][2] + bv0;
            C[(size_t)(r0 + 8) * N + c0 + 1] = acc_h[i][j][3] + acc_ml[i][j][3] + bv1;
        }
    }
}

// ---------------- LIF scans (round-3 versions) --------------------------------
__global__ void lif1_scan_kernel()
{
    int idx = blockIdx.x * blockDim.x + threadIdx.x;
    if (idx >= BB * NH) return;
    float c = g_C1[idx];
    float m = 0.0f;
#pragma unroll
    for (int t = 0; t < TSTEPS; t++) {
        m = BETA * m + c;
        float s = (m - THRESH > 0.0f) ? 1.0f : 0.0f;
        m -= s * THRESH;
        g_spk1[(size_t)t * (BB * NH) + idx] = __float2bfloat16_rn(s);
    }
}

__global__ void lif2_scan_kernel()
{
    int idx = blockIdx.x * blockDim.x + threadIdx.x;
    if (idx >= BB * NH) return;
    float m = 0.0f;
#pragma unroll
    for (int t = 0; t < TSTEPS; t++) {
        float c = g_C2[(size_t)t * (BB * NH) + idx];
        m = BETA * m + c;
        float s = (m - THRESH > 0.0f) ? 1.0f : 0.0f;
        m -= s * THRESH;
        g_spk2[(size_t)t * (BB * NH) + idx] = __float2bfloat16_rn(s);
    }
}

__global__ void lif3_scan_kernel(float* __restrict__ out)
{
    int idx = blockIdx.x * blockDim.x + threadIdx.x;   // b*NC + c
    if (idx >= BB * NC) return;
    int b = idx / NC;
    int c = idx - b * NC;
    float m = 0.0f;
#pragma unroll
    for (int t = 0; t < TSTEPS; t++) {
        float cur = g_C3[(size_t)(t * BB + b) * NCP + c];
        m = BETA * m + cur;
        float s = (m - THRESH > 0.0f) ? 1.0f : 0.0f;
        m -= s * THRESH;
        out[(size_t)t * (BB * NC) + idx] = s;
        out[(size_t)TSTEPS * (BB * NC) + (size_t)t * (BB * NC) + idx] = m;
    }
}

// ---------------- launch ------------------------------------------------------
extern "C" void kernel_launch(void* const* d_in, const int* in_sizes, int n_in,
                              void* d_out, int out_size)
{
    const float* x  = (const float*)d_in[0];
    const float* W1 = (const float*)d_in[1];
    const float* b1 = (const float*)d_in[2];
    const float* W2 = (const float*)d_in[3];
    const float* b2 = (const float*)d_in[4];
    const float* W3 = (const float*)d_in[5];
    const float* b3 = (const float*)d_in[6];
    float* out = (float*)d_out;

    bf16 *w2h, *w2m, *w2l, *w3h, *w3m, *w3l, *spk1, *spk2;
    float *C1, *C2, *C3, *b3p;
    cudaGetSymbolAddress((void**)&w2h, g_w2h); cudaGetSymbolAddress((void**)&w2m, g_w2m);
    cudaGetSymbolAddress((void**)&w2l, g_w2l);
    cudaGetSymbolAddress((void**)&w3h, g_w3h); cudaGetSymbolAddress((void**)&w3m, g_w3m);
    cudaGetSymbolAddress((void**)&w3l, g_w3l);
    cudaGetSymbolAddress((void**)&spk1, g_spk1);
    cudaGetSymbolAddress((void**)&spk2, g_spk2);
    cudaGetSymbolAddress((void**)&C1, g_C1);
    cudaGetSymbolAddress((void**)&C2, g_C2);
    cudaGetSymbolAddress((void**)&C3, g_C3);
    cudaGetSymbolAddress((void**)&b3p, g_b3p);

    // weight splits (exact decompositions)
    conv3_kernel<<<(NH * NH + 255) / 256, 256>>>(W2, w2h, w2m, w2l, NH * NH);
    conv3_w3_kernel<<<(NCP * NH + 255) / 256, 256>>>(W3);
    b3pad_kernel<<<1, 128>>>(b3);

    // GEMM1 (fp32, K-sequential, bitwise = round 3): cur1 = x @ W1^T + b1
    gemm1_f32_kernel<<<dim3(BB / 32, NH / 64), 256>>>(x, W1, b1, C1);
    lif1_scan_kernel<<<(BB * NH + 255) / 256, 256>>>();

    // GEMM2: cur2_all = spk1_all @ (W2h+W2m+W2l)^T + b2   (M=6400, N=2048)
    mma3_gemm_k128<<<dim3(MT / 128, NH / 128), 256>>>(spk1, w2h, w2m, w2l, b2, C2, NH, NH);
    lif2_scan_kernel<<<(BB * NH + 255) / 256, 256>>>();

    // GEMM3 (round-3 kernel): cur3_all = spk2_all @ W3p^T + b3p (M=6400, N=128)
    mma3_gemm<<<dim3(MT / MMA_BM, 1), 256>>>(spk2, w3h, w3m, w3l, b3p, C3, NH, NCP);
    lif3_scan_kernel<<<(BB * NC + 255) / 256, 256>>>(out);
}

// round 7
// speedup vs baseline: 1.5667x; 1.5667x over previous
#include <cuda_runtime.h>
#include <cuda_fp16.h>
#include <cstdint>

#define BB 256
#define NIN 2048
#define NH 2048
#define NC 100
#define NCP 128
#define TSTEPS 25
#define MT (TSTEPS*BB)   // 6400
#define BETA 0.95f
#define THRESH 1.0f
#define RSCALE 2048.0f
#define RINV   4.8828125e-4f   // 1/2048, exact

typedef __half f16;

// ---------------- scratch (device globals; no allocations allowed) -----------
__device__ __align__(256) f16 g_w2h[NH*NH],  g_w2m[NH*NH];
__device__ __align__(256) f16 g_w3h[NCP*NH], g_w3m[NCP*NH];
__device__ __align__(256) float g_b3p[NCP];
__device__ __align__(256) float g_C1[BB*NH];        // cur1 (+b1), loop-invariant
__device__ __align__(256) f16  g_spk1[MT*NH];       // [t][b][n]
__device__ __align__(256) float g_C2[MT*NH];
__device__ __align__(256) f16  g_spk2[MT*NH];
__device__ __align__(256) float g_C3[MT*NCP];

// ---------------- 2-way fp16 split with scaled residual ----------------------
// w = h + m * 2^-11 + err, |err| ~ 2^-28
__global__ void conv2_kernel(const float* __restrict__ src,
                             f16* __restrict__ h, f16* __restrict__ m, int n)
{
    int i = blockIdx.x * blockDim.x + threadIdx.x;
    if (i >= n) return;
    float v  = src[i];
    f16 hv   = __float2half_rn(v);
    float r  = v - __half2float(hv);
    h[i] = hv;
    m[i] = __float2half_rn(r * RSCALE);
}

// W3 padded to 128 rows (rows >= 100 are zero)
__global__ void conv2_w3_kernel(const float* __restrict__ W3)
{
    int i = blockIdx.x * blockDim.x + threadIdx.x;   // 0 .. NCP*NH-1
    if (i >= NCP * NH) return;
    int row = i >> 11;
    float v = (row < NC) ? W3[(size_t)row * NH + (i & (NH - 1))] : 0.0f;
    f16 hv  = __float2half_rn(v);
    float r = v - __half2float(hv);
    g_w3h[i] = hv;
    g_w3m[i] = __float2half_rn(r * RSCALE);
}

__global__ void b3pad_kernel(const float* __restrict__ b3)
{
    int i = threadIdx.x;
    if (i < NCP) g_b3p[i] = (i < NC) ? b3[i] : 0.0f;
}

// ---------------- GEMM1: fp32 SIMT, K sequential (bitwise = round 3/6) -------
__global__ void __launch_bounds__(256)
gemm1_f32_kernel(const float* __restrict__ A, const float* __restrict__ W,
                 const float* __restrict__ bias, float* __restrict__ Cout)
{
    __shared__ float As[16][32];
    __shared__ float Bs[16][64];

    const int bm  = blockIdx.x * 32;
    const int bn  = blockIdx.y * 64;
    const int tid = threadIdx.x;
    const int tr  = tid >> 4;
    const int tc  = tid & 15;
    const int lr  = tid >> 2;
    const int lc  = (tid & 3) << 2;

    float acc[2][4];
#pragma unroll
    for (int i = 0; i < 2; i++)
#pragma unroll
        for (int j = 0; j < 4; j++) acc[i][j] = 0.0f;

    const float* Aptr = A + (size_t)(bm + lr) * NIN + lc;
    const float* Wptr = W + (size_t)(bn + lr) * NIN + lc;

    for (int k0 = 0; k0 < NIN; k0 += 16) {
        if (lr < 32) {
            float4 av = *(const float4*)(Aptr + k0);
            As[lc + 0][lr] = av.x; As[lc + 1][lr] = av.y;
            As[lc + 2][lr] = av.z; As[lc + 3][lr] = av.w;
        }
        {
            float4 wv = *(const float4*)(Wptr + k0);
            Bs[lc + 0][lr] = wv.x; Bs[lc + 1][lr] = wv.y;
            Bs[lc + 2][lr] = wv.z; Bs[lc + 3][lr] = wv.w;
        }
        __syncthreads();
#pragma unroll
        for (int k = 0; k < 16; k++) {
            float a0 = As[k][tr * 2];
            float a1 = As[k][tr * 2 + 1];
            float b[4];
            *(float4*)b = *(const float4*)&Bs[k][tc * 4];
#pragma unroll
            for (int j = 0; j < 4; j++) {
                acc[0][j] += a0 * b[j];
                acc[1][j] += a1 * b[j];
            }
        }
        __syncthreads();
    }

#pragma unroll
    for (int i = 0; i < 2; i++) {
        int r = bm + tr * 2 + i;
#pragma unroll
        for (int j = 0; j < 4; j++) {
            int c = bn + tc * 4 + j;
            Cout[(size_t)r * NH + c] = acc[i][j] + bias[c];
        }
    }
}

// ---------------- MMA helpers -------------------------------------------------
__device__ __forceinline__ uint32_t smem_u32(const void* p) {
    return (uint32_t)__cvta_generic_to_shared(p);
}
__device__ __forceinline__ void cp16(uint32_t dst, const void* src) {
    asm volatile("cp.async.ca.shared.global [%0], [%1], 16;" :: "r"(dst), "l"(src));
}
__device__ __forceinline__ void cp_commit() { asm volatile("cp.async.commit_group;"); }
template<int N> __device__ __forceinline__ void cp_wait() {
    asm volatile("cp.async.wait_group %0;" :: "n"(N));
}
__device__ __forceinline__ void ldm_x4(uint32_t* r, uint32_t addr) {
    asm volatile("ldmatrix.sync.aligned.m8n8.x4.shared.b16 {%0,%1,%2,%3}, [%4];"
                 : "=r"(r[0]), "=r"(r[1]), "=r"(r[2]), "=r"(r[3]) : "r"(addr));
}
__device__ __forceinline__ void mma16816(float* c, const uint32_t* a,
                                          uint32_t b0, uint32_t b1) {
    asm volatile(
        "mma.sync.aligned.m16n8k16.row.col.f32.f16.f16.f32 "
        "{%0,%1,%2,%3}, {%4,%5,%6,%7}, {%8,%9}, {%0,%1,%2,%3};"
        : "+f"(c[0]), "+f"(c[1]), "+f"(c[2]), "+f"(c[3])
        : "r"(a[0]), "r"(a[1]), "r"(a[2]), "r"(a[3]), "r"(b0), "r"(b1));
}

// ======== 2-pass fp16 MMA GEMM: C = A@(B0 + B1*2^-11)^T + bias ===============
// BM=64, BN=128, BK=32; 256 threads = 8 warps (2M x 4N); cp.async double buffer.
#define MMA_BM 64
#define MMA_MI 2
#define A_STG (MMA_BM*40*2)     // 5120 B per stage
#define B_STG (128*40*2)        // 10240 B per stage

__global__ void __launch_bounds__(256)
mma2_gemm(const f16* __restrict__ A,
          const f16* __restrict__ B0, const f16* __restrict__ B1,
          const float* __restrict__ bias, float* __restrict__ C,
          int K, int N)
{
    __shared__ f16 As[2][MMA_BM][40];
    __shared__ f16 Bs[2][128][40];

    const int tid  = threadIdx.x;
    const int lane = tid & 31;
    const int wid  = tid >> 5;
    const int wm   = wid >> 2;
    const int wn   = wid & 3;
    const int g    = lane >> 2;
    const int q    = lane & 3;
    const int bm   = blockIdx.x * MMA_BM;
    const int bn   = blockIdx.y * 128;

    const uint32_t As_base = smem_u32(&As[0][0][0]);
    const uint32_t Bs_base = smem_u32(&Bs[0][0][0]);

    uint32_t a_off[MMA_MI];
#pragma unroll
    for (int i = 0; i < MMA_MI; i++)
        a_off[i] = ((wm * 32 + i * 16 + (lane & 15)) * 40 + ((lane >> 4) & 1) * 8) * 2;
    uint32_t b_off[2];
#pragma unroll
    for (int jj = 0; jj < 2; jj++)
        b_off[jj] = ((wn * 32 + jj * 16 + ((lane >> 4) & 1) * 8 + (lane & 7)) * 40
                     + ((lane >> 3) & 1) * 8) * 2;

    const int arow = tid >> 2, ac8 = (tid & 3) * 8;

    float acc_h[MMA_MI][4][4], acc_m[MMA_MI][4][4];
#pragma unroll
    for (int i = 0; i < MMA_MI; i++)
#pragma unroll
        for (int j = 0; j < 4; j++)
#pragma unroll
            for (int r = 0; r < 4; r++) { acc_h[i][j][r] = 0.0f; acc_m[i][j][r] = 0.0f; }

    const int ktiles = K / 32;
    const int ktot   = ktiles * 2;

    auto issue = [&](int tn, int st) {
        int p  = tn / ktiles;
        int kc = (tn - p * ktiles) * 32;
        const f16* Bp = (p == 0) ? B0 : B1;
        cp16(As_base + st * A_STG + (arow * 40 + ac8) * 2,
             A + (size_t)(bm + arow) * K + kc + ac8);
#pragma unroll
        for (int r = 0; r < 2; r++) {
            int u = tid + r * 256, row = u >> 2, c8 = (u & 3) * 8;
            cp16(Bs_base + st * B_STG + (row * 40 + c8) * 2,
                 Bp + (size_t)(bn + row) * K + kc + c8);
        }
        cp_commit();
    };

    issue(0, 0);

    for (int kt = 0; kt < ktot; kt++) {
        const int st = kt & 1;
        if (kt + 1 < ktot) { issue(kt + 1, (kt + 1) & 1); cp_wait<1>(); }
        else               { cp_wait<0>(); }
        __syncthreads();

        const bool is_h = (kt < ktiles);
#pragma unroll
        for (int kk = 0; kk < 32; kk += 16) {
            uint32_t af[MMA_MI][4], bf[2][4];
#pragma unroll
            for (int i = 0; i < MMA_MI; i++)
                ldm_x4(af[i], As_base + st * A_STG + a_off[i] + kk * 2);
#pragma unroll
            for (int jj = 0; jj < 2; jj++)
                ldm_x4(bf[jj], Bs_base + st * B_STG + b_off[jj] + kk * 2);

            if (is_h) {
#pragma unroll
                for (int i = 0; i < MMA_MI; i++)
#pragma unroll
                    for (int j = 0; j < 4; j++)
                        mma16816(acc_h[i][j], af[i], bf[j >> 1][(j & 1) * 2],
                                 bf[j >> 1][(j & 1) * 2 + 1]);
            } else {
#pragma unroll
                for (int i = 0; i < MMA_MI; i++)
#pragma unroll
                    for (int j = 0; j < 4; j++)
                        mma16816(acc_m[i][j], af[i], bf[j >> 1][(j & 1) * 2],
                                 bf[j >> 1][(j & 1) * 2 + 1]);
            }
        }
        __syncthreads();
    }

    // epilogue: C = (acc_h + acc_m * 2^-11) + bias
#pragma unroll
    for (int i = 0; i < MMA_MI; i++) {
        int r0 = bm + wm * 32 + i * 16 + g;
#pragma unroll
        for (int j = 0; j < 4; j++) {
            int c0 = bn + wn * 32 + j * 8 + q * 2;
            float bv0 = bias[c0], bv1 = bias[c0 + 1];
            C[(size_t)r0 * N + c0]           = (acc_h[i][j][0] + acc_m[i][j][0] * RINV) + bv0;
            C[(size_t)r0 * N + c0 + 1]       = (acc_h[i][j][1] + acc_m[i][j][1] * RINV) + bv1;
            C[(size_t)(r0 + 8) * N + c0]     = (acc_h[i][j][2] + acc_m[i][j][2] * RINV) + bv0;
            C[(size_t)(r0 + 8) * N + c0 + 1] = (acc_h[i][j][3] + acc_m[i][j][3] * RINV) + bv1;
        }
    }
}

// ---------------- LIF scans ---------------------------------------------------
__global__ void lif1_scan_kernel()
{
    int idx = blockIdx.x * blockDim.x + threadIdx.x;
    if (idx >= BB * NH) return;
    float c = g_C1[idx];
    float m = 0.0f;
#pragma unroll
    for (int t = 0; t < TSTEPS; t++) {
        m = BETA * m + c;
        float s = (m - THRESH > 0.0f) ? 1.0f : 0.0f;
        m -= s * THRESH;
        g_spk1[(size_t)t * (BB * NH) + idx] = __float2half_rn(s);
    }
}

__global__ void lif2_scan_kernel()
{
    int idx = blockIdx.x * blockDim.x + threadIdx.x;
    if (idx >= BB * NH) return;
    float m = 0.0f;
#pragma unroll
    for (int t = 0; t < TSTEPS; t++) {
        float c = g_C2[(size_t)t * (BB * NH) + idx];
        m = BETA * m + c;
        float s = (m - THRESH > 0.0f) ? 1.0f : 0.0f;
        m -= s * THRESH;
        g_spk2[(size_t)t * (BB * NH) + idx] = __float2half_rn(s);
    }
}

__global__ void lif3_scan_kernel(float* __restrict__ out)
{
    int idx = blockIdx.x * blockDim.x + threadIdx.x;   // b*NC + c
    if (idx >= BB * NC) return;
    int b = idx / NC;
    int c = idx - b * NC;
    float m = 0.0f;
#pragma unroll
    for (int t = 0; t < TSTEPS; t++) {
        float cur = g_C3[(size_t)(t * BB + b) * NCP + c];
        m = BETA * m + cur;
        float s = (m - THRESH > 0.0f) ? 1.0f : 0.0f;
        m -= s * THRESH;
        out[(size_t)t * (BB * NC) + idx] = s;
        out[(size_t)TSTEPS * (BB * NC) + (size_t)t * (BB * NC) + idx] = m;
    }
}

// ---------------- launch ------------------------------------------------------
extern "C" void kernel_launch(void* const* d_in, const int* in_sizes, int n_in,
                              void* d_out, int out_size)
{
    const float* x  = (const float*)d_in[0];
    const float* W1 = (const float*)d_in[1];
    const float* b1 = (const float*)d_in[2];
    const float* W2 = (const float*)d_in[3];
    const float* b2 = (const float*)d_in[4];
    const float* W3 = (const float*)d_in[5];
    const float* b3 = (const float*)d_in[6];
    float* out = (float*)d_out;

    f16 *w2h, *w2m, *w3h, *w3m, *spk1, *spk2;
    float *C1, *C2, *C3, *b3p;
    cudaGetSymbolAddress((void**)&w2h, g_w2h); cudaGetSymbolAddress((void**)&w2m, g_w2m);
    cudaGetSymbolAddress((void**)&w3h, g_w3h); cudaGetSymbolAddress((void**)&w3m, g_w3m);
    cudaGetSymbolAddress((void**)&spk1, g_spk1);
    cudaGetSymbolAddress((void**)&spk2, g_spk2);
    cudaGetSymbolAddress((void**)&C1, g_C1);
    cudaGetSymbolAddress((void**)&C2, g_C2);
    cudaGetSymbolAddress((void**)&C3, g_C3);
    cudaGetSymbolAddress((void**)&b3p, g_b3p);

    // weight splits (h + m*2^-11, ~22-bit accurate)
    conv2_kernel<<<(NH * NH + 255) / 256, 256>>>(W2, w2h, w2m, NH * NH);
    conv2_w3_kernel<<<(NCP * NH + 255) / 256, 256>>>(W3);
    b3pad_kernel<<<1, 128>>>(b3);

    // GEMM1 (fp32, K-sequential): cur1 = x @ W1^T + b1
    gemm1_f32_kernel<<<dim3(BB / 32, NH / 64), 256>>>(x, W1, b1, C1);
    lif1_scan_kernel<<<(BB * NH + 255) / 256, 256>>>();

    // GEMM2 (2-pass fp16 MMA): cur2_all = spk1_all @ W2^T + b2  (M=6400, N=2048)
    mma2_gemm<<<dim3(MT / MMA_BM, NH / 128), 256>>>(spk1, w2h, w2m, b2, C2, NH, NH);
    lif2_scan_kernel<<<(BB * NH + 255) / 256, 256>>>();

    // GEMM3 (2-pass fp16 MMA): cur3_all = spk2_all @ W3p^T + b3p (M=6400, N=128)
    mma2_gemm<<<dim3(MT / MMA_BM, 1), 256>>>(spk2, w3h, w3m, b3p, C3, NH, NCP);
    lif3_scan_kernel<<<(BB * NC + 255) / 256, 256>>>(out);
}

// round 9
// speedup vs baseline: 1.6060x; 1.0251x over previous
#include <cuda_runtime.h>
#include <cuda_fp16.h>
#include <cstdint>

#define BB 256
#define NIN 2048
#define NH 2048
#define NC 100
#define NCP 128
#define TSTEPS 25
#define MT (TSTEPS*BB)   // 6400
#define BETA 0.95f
#define THRESH 1.0f
#define RSCALE 2048.0f
#define RINV   4.8828125e-4f   // 1/2048, exact

typedef __half f16;

// ---------------- scratch (device globals; no allocations allowed) -----------
__device__ __align__(256) f16 g_w2h[NH*NH],  g_w2m[NH*NH];
__device__ __align__(256) f16 g_w3h[NCP*NH], g_w3m[NCP*NH];
__device__ __align__(256) float g_b3p[NCP];
__device__ __align__(256) float g_C1[BB*NH];        // cur1 (+b1), loop-invariant
__device__ __align__(256) f16  g_spk1[MT*NH];       // [t][b][n]
__device__ __align__(256) float g_C2[MT*NH];
__device__ __align__(256) f16  g_spk2[MT*NH];
__device__ __align__(256) float g_C3[MT*NCP];

// ---------------- 2-way fp16 split with scaled residual (vectorized) ---------
__global__ void conv2v_kernel(const float4* __restrict__ src,
                              __half2* __restrict__ h, __half2* __restrict__ m, int n4)
{
    int i = blockIdx.x * blockDim.x + threadIdx.x;
    if (i >= n4) return;
    float4 v = src[i];
    f16 h0 = __float2half_rn(v.x), h1 = __float2half_rn(v.y);
    f16 h2 = __float2half_rn(v.z), h3 = __float2half_rn(v.w);
    f16 m0 = __float2half_rn((v.x - __half2float(h0)) * RSCALE);
    f16 m1 = __float2half_rn((v.y - __half2float(h1)) * RSCALE);
    f16 m2 = __float2half_rn((v.z - __half2float(h2)) * RSCALE);
    f16 m3 = __float2half_rn((v.w - __half2float(h3)) * RSCALE);
    h[i * 2 + 0] = __halves2half2(h0, h1);
    h[i * 2 + 1] = __halves2half2(h2, h3);
    m[i * 2 + 0] = __halves2half2(m0, m1);
    m[i * 2 + 1] = __halves2half2(m2, m3);
}

// W3 padded to 128 rows (rows >= 100 are zero)
__global__ void conv2_w3_kernel(const float* __restrict__ W3)
{
    int i = blockIdx.x * blockDim.x + threadIdx.x;   // 0 .. NCP*NH-1
    if (i >= NCP * NH) return;
    int row = i >> 11;
    float v = (row < NC) ? W3[(size_t)row * NH + (i & (NH - 1))] : 0.0f;
    f16 hv  = __float2half_rn(v);
    float r = v - __half2float(hv);
    g_w3h[i] = hv;
    g_w3m[i] = __float2half_rn(r * RSCALE);
}

__global__ void b3pad_kernel(const float* __restrict__ b3)
{
    int i = threadIdx.x;
    if (i < NCP) g_b3p[i] = (i < NC) ? b3[i] : 0.0f;
}

// ---------------- GEMM1: fp32 SIMT, K sequential, BK=32 (bitwise = r6/7) -----
// BM=32, BN=64; 256 threads; per-thread tile 2x4. grid (8, 32) = 256 blocks.
__global__ void __launch_bounds__(256)
gemm1_f32_kernel(const float* __restrict__ A, const float* __restrict__ W,
                 const float* __restrict__ bias, float* __restrict__ Cout)
{
    __shared__ float As[32][32];
    __shared__ float Bs[32][64];

    const int bm  = blockIdx.x * 32;
    const int bn  = blockIdx.y * 64;
    const int tid = threadIdx.x;
    const int tr  = tid >> 4;
    const int tc  = tid & 15;
    const int am  = tid >> 3;          // 0..31
    const int akq = (tid & 7) << 2;    // 0..28

    float acc[2][4];
#pragma unroll
    for (int i = 0; i < 2; i++)
#pragma unroll
        for (int j = 0; j < 4; j++) acc[i][j] = 0.0f;

    const float* Aptr = A + (size_t)(bm + am) * NIN + akq;

    for (int k0 = 0; k0 < NIN; k0 += 32) {
        {
            float4 av = *(const float4*)(Aptr + k0);
            As[akq + 0][am] = av.x; As[akq + 1][am] = av.y;
            As[akq + 2][am] = av.z; As[akq + 3][am] = av.w;
        }
#pragma unroll
        for (int r = 0; r < 2; r++) {
            int u = tid + r * 256;
            int nn = u >> 3, kq = (u & 7) << 2;
            float4 wv = *(const float4*)(W + (size_t)(bn + nn) * NIN + k0 + kq);
            Bs[kq + 0][nn] = wv.x; Bs[kq + 1][nn] = wv.y;
            Bs[kq + 2][nn] = wv.z; Bs[kq + 3][nn] = wv.w;
        }
        __syncthreads();
#pragma unroll
        for (int k = 0; k < 32; k++) {
            float a0 = As[k][tr * 2];
            float a1 = As[k][tr * 2 + 1];
            float b[4];
            *(float4*)b = *(const float4*)&Bs[k][tc * 4];
#pragma unroll
            for (int j = 0; j < 4; j++) {
                acc[0][j] += a0 * b[j];
                acc[1][j] += a1 * b[j];
            }
        }
        __syncthreads();
    }

#pragma unroll
    for (int i = 0; i < 2; i++) {
        int r = bm + tr * 2 + i;
#pragma unroll
        for (int j = 0; j < 4; j++) {
            int c = bn + tc * 4 + j;
            Cout[(size_t)r * NH + c] = acc[i][j] + bias[c];
        }
    }
}

// ---------------- MMA helpers -------------------------------------------------
__device__ __forceinline__ uint32_t smem_u32(const void* p) {
    return (uint32_t)__cvta_generic_to_shared(p);
}
__device__ __forceinline__ void cp16(uint32_t dst, const void* src) {
    asm volatile("cp.async.ca.shared.global [%0], [%1], 16;" :: "r"(dst), "l"(src));
}
__device__ __forceinline__ void cp_commit() { asm volatile("cp.async.commit_group;"); }
template<int N> __device__ __forceinline__ void cp_wait() {
    asm volatile("cp.async.wait_group %0;" :: "n"(N));
}
__device__ __forceinline__ void ldm_x4(uint32_t* r, uint32_t addr) {
    asm volatile("ldmatrix.sync.aligned.m8n8.x4.shared.b16 {%0,%1,%2,%3}, [%4];"
                 : "=r"(r[0]), "=r"(r[1]), "=r"(r[2]), "=r"(r[3]) : "r"(addr));
}
__device__ __forceinline__ void mma16816(float* c, const uint32_t* a,
                                          uint32_t b0, uint32_t b1) {
    asm volatile(
        "mma.sync.aligned.m16n8k16.row.col.f32.f16.f16.f32 "
        "{%0,%1,%2,%3}, {%4,%5,%6,%7}, {%8,%9}, {%0,%1,%2,%3};"
        : "+f"(c[0]), "+f"(c[1]), "+f"(c[2]), "+f"(c[3])
        : "r"(a[0]), "r"(a[1]), "r"(a[2]), "r"(a[3]), "r"(b0), "r"(b1));
}

// ======== 2-pass fp16 MMA GEMM: C = A@(B0 + B1*2^-11)^T + bias ===============
// BM=64, BN=128, BK=32; 256 threads = 8 warps (2M x 4N).
// 3-stage cp.async pipeline, ONE __syncthreads per tile. Bitwise = round 7.
#define MMA_BM 64
#define MMA_MI 2
#define NSTG 3
#define A_STG (MMA_BM*40*2)     // 5120 B per stage
#define B_STG (128*40*2)        // 10240 B per stage

__global__ void __launch_bounds__(256, 2)
mma2_gemm(const f16* __restrict__ A,
          const f16* __restrict__ B0, const f16* __restrict__ B1,
          const float* __restrict__ bias, float* __restrict__ C,
          int K, int N)
{
    __shared__ f16 As[NSTG][MMA_BM][40];
    __shared__ f16 Bs[NSTG][128][40];

    const int tid  = threadIdx.x;
    const int lane = tid & 31;
    const int wid  = tid >> 5;
    const int wm   = wid >> 2;
    const int wn   = wid & 3;
    const int g    = lane >> 2;
    const int q    = lane & 3;
    const int bm   = blockIdx.x * MMA_BM;
    const int bn   = blockIdx.y * 128;

    const uint32_t As_base = smem_u32(&As[0][0][0]);
    const uint32_t Bs_base = smem_u32(&Bs[0][0][0]);

    uint32_t a_off[MMA_MI];
#pragma unroll
    for (int i = 0; i < MMA_MI; i++)
        a_off[i] = ((wm * 32 + i * 16 + (lane & 15)) * 40 + ((lane >> 4) & 1) * 8) * 2;
    uint32_t b_off[2];
#pragma unroll
    for (int jj = 0; jj < 2; jj++)
        b_off[jj] = ((wn * 32 + jj * 16 + ((lane >> 4) & 1) * 8 + (lane & 7)) * 40
                     + ((lane >> 3) & 1) * 8) * 2;

    const int arow = tid >> 2, ac8 = (tid & 3) * 8;

    float acc_h[MMA_MI][4][4], acc_m[MMA_MI][4][4];
#pragma unroll
    for (int i = 0; i < MMA_MI; i++)
#pragma unroll
        for (int j = 0; j < 4; j++)
#pragma unroll
            for (int r = 0; r < 4; r++) { acc_h[i][j][r] = 0.0f; acc_m[i][j][r] = 0.0f; }

    const int ktiles = K / 32;
    const int ktot   = ktiles * 2;

    auto issue = [&](int tn, int st) {
        int p  = (tn >= ktiles) ? 1 : 0;
        int kc = (tn - p * ktiles) * 32;
        const f16* Bp = (p == 0) ? B0 : B1;
        cp16(As_base + st * A_STG + (arow * 40 + ac8) * 2,
             A + (size_t)(bm + arow) * K + kc + ac8);
#pragma unroll
        for (int r = 0; r < 2; r++) {
            int u = tid + r * 256, row = u >> 2, c8 = (u & 3) * 8;
            cp16(Bs_base + st * B_STG + (row * 40 + c8) * 2,
                 Bp + (size_t)(bn + row) * K + kc + c8);
        }
        cp_commit();
    };

    issue(0, 0);
    issue(1, 1);

    for (int kt = 0; kt < ktot; kt++) {
        const int st = kt % NSTG;
        // tiles kt..kt+1 may be outstanding; leave newest pending -> tile kt done
        if (kt + 2 < ktot) cp_wait<1>();
        else               cp_wait<0>();
        __syncthreads();   // all warps done with tile kt-1; tile kt visible
        if (kt + 2 < ktot) issue(kt + 2, (kt + 2) % NSTG);  // overwrites stage of kt-1

        const bool is_h = (kt < ktiles);
#pragma unroll
        for (int kk = 0; kk < 32; kk += 16) {
            uint32_t af[MMA_MI][4], bf[2][4];
#pragma unroll
            for (int i = 0; i < MMA_MI; i++)
                ldm_x4(af[i], As_base + st * A_STG + a_off[i] + kk * 2);
#pragma unroll
            for (int jj = 0; jj < 2; jj++)
                ldm_x4(bf[jj], Bs_base + st * B_STG + b_off[jj] + kk * 2);

            if (is_h) {
#pragma unroll
                for (int i = 0; i < MMA_MI; i++)
#pragma unroll
                    for (int j = 0; j < 4; j++)
                        mma16816(acc_h[i][j], af[i], bf[j >> 1][(j & 1) * 2],
                                 bf[j >> 1][(j & 1) * 2 + 1]);
            } else {
#pragma unroll
                for (int i = 0; i < MMA_MI; i++)
#pragma unroll
                    for (int j = 0; j < 4; j++)
                        mma16816(acc_m[i][j], af[i], bf[j >> 1][(j & 1) * 2],
                                 bf[j >> 1][(j & 1) * 2 + 1]);
            }
        }
    }

    // epilogue: C = (acc_h + acc_m * 2^-11) + bias
#pragma unroll
    for (int i = 0; i < MMA_MI; i++) {
        int r0 = bm + wm * 32 + i * 16 + g;
#pragma unroll
        for (int j = 0; j < 4; j++) {
            int c0 = bn + wn * 32 + j * 8 + q * 2;
            float bv0 = bias[c0], bv1 = bias[c0 + 1];
            C[(size_t)r0 * N + c0]           = (acc_h[i][j][0] + acc_m[i][j][0] * RINV) + bv0;
            C[(size_t)r0 * N + c0 + 1]       = (acc_h[i][j][1] + acc_m[i][j][1] * RINV) + bv1;
            C[(size_t)(r0 + 8) * N + c0]     = (acc_h[i][j][2] + acc_m[i][j][2] * RINV) + bv0;
            C[(size_t)(r0 + 8) * N + c0 + 1] = (acc_h[i][j][3] + acc_m[i][j][3] * RINV) + bv1;
        }
    }
}

// ---------------- LIF scans ---------------------------------------------------
__global__ void lif1_scan_kernel()
{
    int idx = blockIdx.x * blockDim.x + threadIdx.x;
    if (idx >= BB * NH) return;
    float c = g_C1[idx];
    float m = 0.0f;
#pragma unroll
    for (int t = 0; t < TSTEPS; t++) {
        m = BETA * m + c;
        float s = (m - THRESH > 0.0f) ? 1.0f : 0.0f;
        m -= s * THRESH;
        g_spk1[(size_t)t * (BB * NH) + idx] = __float2half_rn(s);
    }
}

__global__ void lif2_scan_kernel()
{
    int idx = blockIdx.x * blockDim.x + threadIdx.x;
    if (idx >= BB * NH) return;
    float m = 0.0f;
#pragma unroll
    for (int t = 0; t < TSTEPS; t++) {
        float c = g_C2[(size_t)t * (BB * NH) + idx];
        m = BETA * m + c;
        float s = (m - THRESH > 0.0f) ? 1.0f : 0.0f;
        m -= s * THRESH;
        g_spk2[(size_t)t * (BB * NH) + idx] = __float2half_rn(s);
    }
}

__global__ void lif3_scan_kernel(float* __restrict__ out)
{
    int idx = blockIdx.x * blockDim.x + threadIdx.x;   // b*NC + c
    if (idx >= BB * NC) return;
    int b = idx / NC;
    int c = idx - b * NC;
    float m = 0.0f;
#pragma unroll
    for (int t = 0; t < TSTEPS; t++) {
        float cur = g_C3[(size_t)(t * BB + b) * NCP + c];
        m = BETA * m + cur;
        float s = (m - THRESH > 0.0f) ? 1.0f : 0.0f;
        m -= s * THRESH;
        out[(size_t)t * (BB * NC) + idx] = s;
        out[(size_t)TSTEPS * (BB * NC) + (size_t)t * (BB * NC) + idx] = m;
    }
}

// ---------------- launch ------------------------------------------------------
extern "C" void kernel_launch(void* const* d_in, const int* in_sizes, int n_in,
                              void* d_out, int out_size)
{
    const float* x  = (const float*)d_in[0];
    const float* W1 = (const float*)d_in[1];
    const float* b1 = (const float*)d_in[2];
    const float* W2 = (const float*)d_in[3];
    const float* b2 = (const float*)d_in[4];
    const float* W3 = (const float*)d_in[5];
    const float* b3 = (const float*)d_in[6];
    float* out = (float*)d_out;

    f16 *w2h, *w2m, *w3h, *w3m, *spk1, *spk2;
    float *C1, *C2, *C3, *b3p;
    cudaGetSymbolAddress((void**)&w2h, g_w2h); cudaGetSymbolAddress((void**)&w2m, g_w2m);
    cudaGetSymbolAddress((void**)&w3h, g_w3h); cudaGetSymbolAddress((void**)&w3m, g_w3m);
    cudaGetSymbolAddress((void**)&spk1, g_spk1);
    cudaGetSymbolAddress((void**)&spk2, g_spk2);
    cudaGetSymbolAddress((void**)&C1, g_C1);
    cudaGetSymbolAddress((void**)&C2, g_C2);
    cudaGetSymbolAddress((void**)&C3, g_C3);
    cudaGetSymbolAddress((void**)&b3p, g_b3p);

    // weight splits (h + m*2^-11, ~22-bit accurate)
    conv2v_kernel<<<(NH * NH / 4 + 255) / 256, 256>>>(
        (const float4*)W2, (__half2*)w2h, (__half2*)w2m, NH * NH / 4);
    conv2_w3_kernel<<<(NCP * NH + 255) / 256, 256>>>(W3);
    b3pad_kernel<<<1, 128>>>(b3);

    // GEMM1 (fp32, K-sequential, bitwise = round 7): cur1 = x @ W1^T + b1
    gemm1_f32_kernel<<<dim3(BB / 32, NH / 64), 256>>>(x, W1, b1, C1);
    lif1_scan_kernel<<<(BB * NH + 255) / 256, 256>>>();

    // GEMM2 (2-pass fp16 MMA, 3-stage): cur2_all = spk1_all @ W2^T + b2
    mma2_gemm<<<dim3(MT / MMA_BM, NH / 128), 256>>>(spk1, w2h, w2m, b2, C2, NH, NH);
    lif2_scan_kernel<<<(BB * NH + 255) / 256, 256>>>();

    // GEMM3 (2-pass fp16 MMA, 3-stage): cur3_all = spk2_all @ W3p^T + b3p
    mma2_gemm<<<dim3(MT / MMA_BM, 1), 256>>>(spk2, w3h, w3m, b3p, C3, NH, NCP);
    lif3_scan_kernel<<<(BB * NC + 255) / 256, 256>>>(out);
}

// round 11
// speedup vs baseline: 1.8123x; 1.1284x over previous
#include <cuda_runtime.h>
#include <cuda_fp16.h>
#include <cstdint>

#define BB 256
#define NIN 2048
#define NH 2048
#define NC 100
#define NCP 128
#define TSTEPS 25
#define MT (TSTEPS*BB)   // 6400
#define BETA 0.95f
#define THRESH 1.0f
#define RSCALE 2048.0f
#define RINV   4.8828125e-4f   // 1/2048, exact

typedef __half f16;

// ---------------- scratch (device globals; no allocations allowed) -----------
__device__ __align__(256) f16 g_w2h[NH*NH],  g_w2m[NH*NH];
__device__ __align__(256) f16 g_w3h[NCP*NH], g_w3m[NCP*NH];
__device__ __align__(256) float g_b3p[NCP];
__device__ __align__(256) float g_C1[BB*NH];        // cur1 (+b1), loop-invariant
__device__ __align__(256) f16  g_spk1[MT*NH];       // [t][b][n]
__device__ __align__(256) float g_C2[MT*NH];
__device__ __align__(256) f16  g_spk2[MT*NH];
__device__ __align__(256) float g_C3[MT*NCP];

// ---------------- 2-way fp16 split with scaled residual (vectorized) ---------
__global__ void conv2v_kernel(const float4* __restrict__ src,
                              __half2* __restrict__ h, __half2* __restrict__ m, int n4)
{
    int i = blockIdx.x * blockDim.x + threadIdx.x;
    if (i >= n4) return;
    float4 v = src[i];
    f16 h0 = __float2half_rn(v.x), h1 = __float2half_rn(v.y);
    f16 h2 = __float2half_rn(v.z), h3 = __float2half_rn(v.w);
    f16 m0 = __float2half_rn((v.x - __half2float(h0)) * RSCALE);
    f16 m1 = __float2half_rn((v.y - __half2float(h1)) * RSCALE);
    f16 m2 = __float2half_rn((v.z - __half2float(h2)) * RSCALE);
    f16 m3 = __float2half_rn((v.w - __half2float(h3)) * RSCALE);
    h[i * 2 + 0] = __halves2half2(h0, h1);
    h[i * 2 + 1] = __halves2half2(h2, h3);
    m[i * 2 + 0] = __halves2half2(m0, m1);
    m[i * 2 + 1] = __halves2half2(m2, m3);
}

// W3 padded to 128 rows (rows >= 100 are zero)
__global__ void conv2_w3_kernel(const float* __restrict__ W3)
{
    int i = blockIdx.x * blockDim.x + threadIdx.x;   // 0 .. NCP*NH-1
    if (i >= NCP * NH) return;
    int row = i >> 11;
    float v = (row < NC) ? W3[(size_t)row * NH + (i & (NH - 1))] : 0.0f;
    f16 hv  = __float2half_rn(v);
    float r = v - __half2float(hv);
    g_w3h[i] = hv;
    g_w3m[i] = __float2half_rn(r * RSCALE);
}

__global__ void b3pad_kernel(const float* __restrict__ b3)
{
    int i = threadIdx.x;
    if (i < NCP) g_b3p[i] = (i < NC) ? b3[i] : 0.0f;
}

// ---------------- GEMM1: fp32 SIMT, K sequential, BK=32 (bitwise = r7/9) -----
__global__ void __launch_bounds__(256)
gemm1_f32_kernel(const float* __restrict__ A, const float* __restrict__ W,
                 const float* __restrict__ bias, float* __restrict__ Cout)
{
    __shared__ float As[32][32];
    __shared__ float Bs[32][64];

    const int bm  = blockIdx.x * 32;
    const int bn  = blockIdx.y * 64;
    const int tid = threadIdx.x;
    const int tr  = tid >> 4;
    const int tc  = tid & 15;
    const int am  = tid >> 3;
    const int akq = (tid & 7) << 2;

    float acc[2][4];
#pragma unroll
    for (int i = 0; i < 2; i++)
#pragma unroll
        for (int j = 0; j < 4; j++) acc[i][j] = 0.0f;

    const float* Aptr = A + (size_t)(bm + am) * NIN + akq;

    for (int k0 = 0; k0 < NIN; k0 += 32) {
        {
            float4 av = *(const float4*)(Aptr + k0);
            As[akq + 0][am] = av.x; As[akq + 1][am] = av.y;
            As[akq + 2][am] = av.z; As[akq + 3][am] = av.w;
        }
#pragma unroll
        for (int r = 0; r < 2; r++) {
            int u = tid + r * 256;
            int nn = u >> 3, kq = (u & 7) << 2;
            float4 wv = *(const float4*)(W + (size_t)(bn + nn) * NIN + k0 + kq);
            Bs[kq + 0][nn] = wv.x; Bs[kq + 1][nn] = wv.y;
            Bs[kq + 2][nn] = wv.z; Bs[kq + 3][nn] = wv.w;
        }
        __syncthreads();
#pragma unroll
        for (int k = 0; k < 32; k++) {
            float a0 = As[k][tr * 2];
            float a1 = As[k][tr * 2 + 1];
            float b[4];
            *(float4*)b = *(const float4*)&Bs[k][tc * 4];
#pragma unroll
            for (int j = 0; j < 4; j++) {
                acc[0][j] += a0 * b[j];
                acc[1][j] += a1 * b[j];
            }
        }
        __syncthreads();
    }

#pragma unroll
    for (int i = 0; i < 2; i++) {
        int r = bm + tr * 2 + i;
#pragma unroll
        for (int j = 0; j < 4; j++) {
            int c = bn + tc * 4 + j;
            Cout[(size_t)r * NH + c] = acc[i][j] + bias[c];
        }
    }
}

// ---------------- MMA helpers -------------------------------------------------
__device__ __forceinline__ uint32_t smem_u32(const void* p) {
    return (uint32_t)__cvta_generic_to_shared(p);
}
__device__ __forceinline__ void cp16(uint32_t dst, const void* src) {
    asm volatile("cp.async.ca.shared.global [%0], [%1], 16;" :: "r"(dst), "l"(src));
}
__device__ __forceinline__ void cp_commit() { asm volatile("cp.async.commit_group;"); }
template<int N> __device__ __forceinline__ void cp_wait() {
    asm volatile("cp.async.wait_group %0;" :: "n"(N));
}
__device__ __forceinline__ void ldm_x4(uint32_t* r, uint32_t addr) {
    asm volatile("ldmatrix.sync.aligned.m8n8.x4.shared.b16 {%0,%1,%2,%3}, [%4];"
                 : "=r"(r[0]), "=r"(r[1]), "=r"(r[2]), "=r"(r[3]) : "r"(addr));
}
__device__ __forceinline__ void mma16816(float* c, const uint32_t* a,
                                          uint32_t b0, uint32_t b1) {
    asm volatile(
        "mma.sync.aligned.m16n8k16.row.col.f32.f16.f16.f32 "
        "{%0,%1,%2,%3}, {%4,%5,%6,%7}, {%8,%9}, {%0,%1,%2,%3};"
        : "+f"(c[0]), "+f"(c[1]), "+f"(c[2]), "+f"(c[3])
        : "r"(a[0]), "r"(a[1]), "r"(a[2]), "r"(a[3]), "r"(b0), "r"(b1));
}

// ======== A-shared 2-chain fp16 MMA GEMM: C = A@(B0 + B1*2^-11)^T + bias =====
// BM=64, BN=128, BK=32; 256 threads = 8 warps (2M x 4N).
// Per k-tile: A loaded ONCE, both B tiles; 8 mma -> acc_h, 8 mma -> acc_m.
// Per-accumulator K order unchanged => bitwise identical to round 7/9.
// 3-stage cp.async pipeline, dynamic smem (76.8 KB), 2 CTAs/SM.
#define MMA_BM 64
#define MMA_MI 2
#define NSTG 3
#define A_STG 5120u            // 64*40*2 per stage
#define B_STG 10240u           // 128*40*2 per pass
#define AB_TOT (NSTG*A_STG)    // 15360
#define STG_B  (2u*B_STG)      // 20480 per stage (both passes)
#define SM_DYN (AB_TOT + NSTG*STG_B)   // 76800

__global__ void __launch_bounds__(256, 2)
mma2_gemm(const f16* __restrict__ A,
          const f16* __restrict__ B0, const f16* __restrict__ B1,
          const float* __restrict__ bias, float* __restrict__ C,
          int K, int N)
{
    extern __shared__ f16 smem[];
    const uint32_t sb = smem_u32(smem);

    const int tid  = threadIdx.x;
    const int lane = tid & 31;
    const int wid  = tid >> 5;
    const int wm   = wid >> 2;
    const int wn   = wid & 3;
    const int g    = lane >> 2;
    const int q    = lane & 3;
    const int bm   = blockIdx.x * MMA_BM;
    const int bn   = blockIdx.y * 128;

    uint32_t a_off[MMA_MI];
#pragma unroll
    for (int i = 0; i < MMA_MI; i++)
        a_off[i] = ((wm * 32 + i * 16 + (lane & 15)) * 40 + ((lane >> 4) & 1) * 8) * 2;
    uint32_t b_off[2];
#pragma unroll
    for (int jj = 0; jj < 2; jj++)
        b_off[jj] = ((wn * 32 + jj * 16 + ((lane >> 4) & 1) * 8 + (lane & 7)) * 40
                     + ((lane >> 3) & 1) * 8) * 2;

    const int arow = tid >> 2, ac8 = (tid & 3) * 8;

    float acc_h[MMA_MI][4][4], acc_m[MMA_MI][4][4];
#pragma unroll
    for (int i = 0; i < MMA_MI; i++)
#pragma unroll
        for (int j = 0; j < 4; j++)
#pragma unroll
            for (int r = 0; r < 4; r++) { acc_h[i][j][r] = 0.0f; acc_m[i][j][r] = 0.0f; }

    const int ktot = K / 32;   // 64 tiles; each tile serves both chains

    auto issue = [&](int tn, int st) {
        int kc = tn * 32;
        cp16(sb + st * A_STG + (arow * 40 + ac8) * 2,
             A + (size_t)(bm + arow) * K + kc + ac8);
        const uint32_t bbase = sb + AB_TOT + st * STG_B;
#pragma unroll
        for (int r = 0; r < 4; r++) {
            int u = tid + r * 256;          // 0..1023
            int p = u >> 9;                 // 0: B0, 1: B1
            int v = u & 511;
            int row = v >> 2, c8 = (v & 3) * 8;
            const f16* Bp = (p == 0) ? B0 : B1;
            cp16(bbase + p * B_STG + (row * 40 + c8) * 2,
                 Bp + (size_t)(bn + row) * K + kc + c8);
        }
        cp_commit();
    };

    issue(0, 0);
    issue(1, 1);

    for (int kt = 0; kt < ktot; kt++) {
        const int st = kt % NSTG;
        if (kt + 2 < ktot) cp_wait<1>();
        else               cp_wait<0>();
        __syncthreads();
        if (kt + 2 < ktot) issue(kt + 2, (kt + 2) % NSTG);

        const uint32_t abase = sb + st * A_STG;
        const uint32_t hbase = sb + AB_TOT + st * STG_B;
        const uint32_t mbase = hbase + B_STG;
#pragma unroll
        for (int kk = 0; kk < 32; kk += 16) {
            uint32_t af[MMA_MI][4], bfh[2][4], bfm[2][4];
#pragma unroll
            for (int i = 0; i < MMA_MI; i++)
                ldm_x4(af[i], abase + a_off[i] + kk * 2);
#pragma unroll
            for (int jj = 0; jj < 2; jj++) {
                ldm_x4(bfh[jj], hbase + b_off[jj] + kk * 2);
                ldm_x4(bfm[jj], mbase + b_off[jj] + kk * 2);
            }
#pragma unroll
            for (int i = 0; i < MMA_MI; i++)
#pragma unroll
                for (int j = 0; j < 4; j++) {
                    mma16816(acc_h[i][j], af[i], bfh[j >> 1][(j & 1) * 2],
                             bfh[j >> 1][(j & 1) * 2 + 1]);
                    mma16816(acc_m[i][j], af[i], bfm[j >> 1][(j & 1) * 2],
                             bfm[j >> 1][(j & 1) * 2 + 1]);
                }
        }
    }

    // epilogue: C = (acc_h + acc_m * 2^-11) + bias  (identical to round 7/9)
#pragma unroll
    for (int i = 0; i < MMA_MI; i++) {
        int r0 = bm + wm * 32 + i * 16 + g;
#pragma unroll
        for (int j = 0; j < 4; j++) {
            int c0 = bn + wn * 32 + j * 8 + q * 2;
            float bv0 = bias[c0], bv1 = bias[c0 + 1];
            C[(size_t)r0 * N + c0]           = (acc_h[i][j][0] + acc_m[i][j][0] * RINV) + bv0;
            C[(size_t)r0 * N + c0 + 1]       = (acc_h[i][j][1] + acc_m[i][j][1] * RINV) + bv1;
            C[(size_t)(r0 + 8) * N + c0]     = (acc_h[i][j][2] + acc_m[i][j][2] * RINV) + bv0;
            C[(size_t)(r0 + 8) * N + c0 + 1] = (acc_h[i][j][3] + acc_m[i][j][3] * RINV) + bv1;
        }
    }
}

// ---------------- LIF scans ---------------------------------------------------
__global__ void lif1_scan_kernel()
{
    int idx = blockIdx.x * blockDim.x + threadIdx.x;
    if (idx >= BB * NH) return;
    float c = g_C1[idx];
    float m = 0.0f;
#pragma unroll
    for (int t = 0; t < TSTEPS; t++) {
        m = BETA * m + c;
        float s = (m - THRESH > 0.0f) ? 1.0f : 0.0f;
        m -= s * THRESH;
        g_spk1[(size_t)t * (BB * NH) + idx] = __float2half_rn(s);
    }
}

__global__ void lif2_scan_kernel()
{
    int idx = blockIdx.x * blockDim.x + threadIdx.x;
    if (idx >= BB * NH) return;
    float m = 0.0f;
#pragma unroll
    for (int t = 0; t < TSTEPS; t++) {
        float c = g_C2[(size_t)t * (BB * NH) + idx];
        m = BETA * m + c;
        float s = (m - THRESH > 0.0f) ? 1.0f : 0.0f;
        m -= s * THRESH;
        g_spk2[(size_t)t * (BB * NH) + idx] = __float2half_rn(s);
    }
}

__global__ void lif3_scan_kernel(float* __restrict__ out)
{
    int idx = blockIdx.x * blockDim.x + threadIdx.x;   // b*NC + c
    if (idx >= BB * NC) return;
    int b = idx / NC;
    int c = idx - b * NC;
    float m = 0.0f;
#pragma unroll
    for (int t = 0; t < TSTEPS; t++) {
        float cur = g_C3[(size_t)(t * BB + b) * NCP + c];
        m = BETA * m + cur;
        float s = (m - THRESH > 0.0f) ? 1.0f : 0.0f;
        m -= s * THRESH;
        out[(size_t)t * (BB * NC) + idx] = s;
        out[(size_t)TSTEPS * (BB * NC) + (size_t)t * (BB * NC) + idx] = m;
    }
}

// ---------------- launch ------------------------------------------------------
extern "C" void kernel_launch(void* const* d_in, const int* in_sizes, int n_in,
                              void* d_out, int out_size)
{
    const float* x  = (const float*)d_in[0];
    const float* W1 = (const float*)d_in[1];
    const float* b1 = (const float*)d_in[2];
    const float* W2 = (const float*)d_in[3];
    const float* b2 = (const float*)d_in[4];
    const float* W3 = (const float*)d_in[5];
    const float* b3 = (const float*)d_in[6];
    float* out = (float*)d_out;

    f16 *w2h, *w2m, *w3h, *w3m, *spk1, *spk2;
    float *C1, *C2, *C3, *b3p;
    cudaGetSymbolAddress((void**)&w2h, g_w2h); cudaGetSymbolAddress((void**)&w2m, g_w2m);
    cudaGetSymbolAddress((void**)&w3h, g_w3h); cudaGetSymbolAddress((void**)&w3m, g_w3m);
    cudaGetSymbolAddress((void**)&spk1, g_spk1);
    cudaGetSymbolAddress((void**)&spk2, g_spk2);
    cudaGetSymbolAddress((void**)&C1, g_C1);
    cudaGetSymbolAddress((void**)&C2, g_C2);
    cudaGetSymbolAddress((void**)&C3, g_C3);
    cudaGetSymbolAddress((void**)&b3p, g_b3p);

    cudaFuncSetAttribute(mma2_gemm, cudaFuncAttributeMaxDynamicSharedMemorySize, SM_DYN);

    // weight splits (h + m*2^-11, ~22-bit accurate)
    conv2v_kernel<<<(NH * NH / 4 + 255) / 256, 256>>>(
        (const float4*)W2, (__half2*)w2h, (__half2*)w2m, NH * NH / 4);
    conv2_w3_kernel<<<(NCP * NH + 255) / 256, 256>>>(W3);
    b3pad_kernel<<<1, 128>>>(b3);

    // GEMM1 (fp32, K-sequential): cur1 = x @ W1^T + b1
    gemm1_f32_kernel<<<dim3(BB / 32, NH / 64), 256>>>(x, W1, b1, C1);
    lif1_scan_kernel<<<(BB * NH + 255) / 256, 256>>>();

    // GEMM2 (A-shared 2-chain fp16 MMA): cur2_all = spk1_all @ W2^T + b2
    mma2_gemm<<<dim3(MT / MMA_BM, NH / 128), 256, SM_DYN>>>(spk1, w2h, w2m, b2, C2, NH, NH);
    lif2_scan_kernel<<<(BB * NH + 255) / 256, 256>>>();

    // GEMM3 (same kernel): cur3_all = spk2_all @ W3p^T + b3p
    mma2_gemm<<<dim3(MT / MMA_BM, 1), 256, SM_DYN>>>(spk2, w3h, w3m, b3p, C3, NH, NCP);
    lif3_scan_kernel<<<(BB * NC + 255) / 256, 256>>>(out);
}